// round 10
// baseline (speedup 1.0000x reference)
#include <cuda_runtime.h>
#include <cuda_fp16.h>
#include <math.h>
#include <stdint.h>

#define BSZ  16
#define CDIM 384
#define LDIM 4096
#define PDIM 192
#define BLTOK (BSZ*LDIM)      // 65536
#define NCH  64
#define TCH  64
#define KDIM 384

// ---------------- static scratch (no allocations allowed) ----------------
__device__ float g_y [(size_t)BLTOK*CDIM];
__device__ float g_lam [2*PDIM];
__device__ float g_lamT[2*PDIM];
__device__ float g_carry[(size_t)BSZ*NCH*CDIM];

// fp16 operands; lo-arrays only where an epilogue residual needs full accuracy
__device__ __half g_buf[(size_t)BLTOK*CDIM];   // Bu fp16 (pre-scan)
__device__ __half g_fxh[(size_t)BLTOK*CDIM], g_fxl[(size_t)BLTOK*CDIM];
__device__ __half g_buh[(size_t)BLTOK*CDIM];   // xs fp16 (post-scan)
__device__ __half g_fyh[(size_t)BLTOK*CDIM], g_fyl[(size_t)BLTOK*CDIM];
__device__ __half g_ggh[(size_t)BLTOK*CDIM];
__device__ __half g_wb[CDIM*CDIM];
__device__ __half g_wc[CDIM*CDIM];
__device__ __half g_we[2*CDIM*CDIM];   // interleaved z1/z2 rows
__device__ __half g_wd[CDIM*CDIM];

__device__ __forceinline__ float gelu_f(float v){
    return 0.5f*v*(1.0f + erff(v*0.70710678118654752f));
}
__device__ __forceinline__ void split_hl(float v, __half& h, __half& l){
    h = __float2half_rn(v);
    l = __float2half_rn(v - __half2float(h));
}
__device__ __forceinline__ uint32_t smem_u32(const void* p){
    uint32_t a;
    asm("{ .reg .u64 t; cvta.to.shared.u64 t, %1; cvt.u32.u64 %0, t; }" : "=r"(a) : "l"(p));
    return a;
}

// ---------------- MMA / ldmatrix / cp.async primitives (sm_80+ neutral PTX) ----------------
#define CP16(sa, ga)  asm volatile("cp.async.cg.shared.global [%0], [%1], 16;" :: "r"(sa), "l"(ga))
#define CPCOMMIT()    asm volatile("cp.async.commit_group;")
#define CPWAIT(n)     asm volatile("cp.async.wait_group %0;" :: "n"(n))

#define LDSM4(r, addr) asm volatile( \
    "ldmatrix.sync.aligned.m8n8.x4.shared.b16 {%0,%1,%2,%3}, [%4];" \
    : "=r"((r)[0]),"=r"((r)[1]),"=r"((r)[2]),"=r"((r)[3]) : "r"(addr))

#define MMA(d, a, b0v, b1v) asm volatile( \
    "mma.sync.aligned.m16n8k16.row.col.f32.f16.f16.f32 " \
    "{%0,%1,%2,%3},{%4,%5,%6,%7},{%8,%9},{%0,%1,%2,%3};" \
    : "+f"((d)[0]),"+f"((d)[1]),"+f"((d)[2]),"+f"((d)[3]) \
    : "r"((a)[0]),"r"((a)[1]),"r"((a)[2]),"r"((a)[3]),"r"(b0v),"r"(b1v))

// ============ fp16 single-pass NT GEMM: C[M,*] = A[M,384] @ B[*,384]^T ============
// tile 128x128, BK=64, 3-stage cp.async, 4 warps (2x2), warp tile 64x64
// stage layout: A @0 (128x144B), B @18432 ; stage stride 36864 ; rows padded to 144B
// EPI 1: f=e0h+e0l; v=acc+e1[n]*f; Cout=gelu(v)+f   (fp32)
// EPI 3: GEGLU pairs -> smem staged -> outH fp16 [BL, 384]
// EPI 4: f=e0h+e0l; o=acc+f; write Cout transposed [B,C,L] via smem staging
// EPI 5: plain fp16 out -> outH
template<int EPI>
__global__ __launch_bounds__(128,2) void mma_gemm(
    const __half* __restrict__ Ah,
    const __half* __restrict__ Bm,
    float* __restrict__ Cout, int Nout,
    __half* __restrict__ outH,
    const __half* __restrict__ e0h, const __half* __restrict__ e0l,
    const float* __restrict__ e1)
{
    extern __shared__ char smem[];
    uint32_t sb = smem_u32(smem);
    const int tid = threadIdx.x;
    const int bm = blockIdx.y*128, bn = blockIdx.x*128;

    // ---- load indexing: 128 rows x 8 segs of 16B per array; 8 row-groups/thread ----
    const int lr  = tid >> 3;          // row 0..15 (+16*h)
    const int seg = tid & 7;           // 16B segment within 128B row
    const __half* pa0 = Ah + (size_t)(bm+lr)*KDIM + seg*8;
    const __half* pb0 = Bm + (size_t)(bn+lr)*KDIM + seg*8;
    const uint32_t s0 = lr*144 + seg*16;

    // ---- compute indexing: warp grid 2x2, warp tile 64x64 ----
    const int lane = tid & 31, w = tid >> 5;
    const int wm = (w >> 1)*64, wn = (w & 1)*64;
    const uint32_t aoff = (uint32_t)(wm + (lane & 15))*144 + (lane >> 4)*16;
    const int bg = lane >> 3, blg = lane & 7;
    const uint32_t boff = (uint32_t)(wn + (bg >> 1)*8 + blg)*144 + (bg & 1)*16;

    float acc[4][8][4];
    #pragma unroll
    for (int i=0;i<4;i++)
        #pragma unroll
        for (int j=0;j<8;j++)
            #pragma unroll
            for (int q=0;q<4;q++) acc[i][j][q]=0.f;

    auto issue = [&](int st, int kc){
        uint32_t sbase = sb + st*36864;
        #pragma unroll
        for (int h = 0; h < 8; h++){
            size_t rofs = (size_t)kc + (size_t)h*16*KDIM;
            uint32_t sa = sbase + s0 + h*16*144;
            CP16(sa,         pa0 + rofs);
            CP16(sa + 18432, pb0 + rofs);
        }
        CPCOMMIT();
    };

    issue(0, 0);
    issue(1, 64);
    int stg = 0;                        // stage of chunk c
    #pragma unroll 1
    for (int c = 0; c < 6; c++){
        if (c < 5) { CPWAIT(1); } else { CPWAIT(0); }
        __syncthreads();
        if (c + 2 < 6){
            int st2 = stg + 2; if (st2 >= 3) st2 -= 3;
            issue(st2, (c+2)*64);
        }
        uint32_t base = sb + stg*36864;
        #pragma unroll
        for (int ks = 0; ks < 4; ks++){
            uint32_t kb = ks*32;
            uint32_t a[4][4], bf[8][2], t[4];
            #pragma unroll
            for (int i=0;i<4;i++) LDSM4(a[i], base + aoff + i*16*144 + kb);
            #pragma unroll
            for (int jp=0;jp<4;jp++){
                LDSM4(t, base + 18432 + boff + jp*16*144 + kb);
                bf[2*jp][0]=t[0]; bf[2*jp][1]=t[1]; bf[2*jp+1][0]=t[2]; bf[2*jp+1][1]=t[3];
            }
            #pragma unroll
            for (int i=0;i<4;i++)
                #pragma unroll
                for (int j=0;j<8;j++) MMA(acc[i][j], a[i], bf[j][0], bf[j][1]);
        }
        if (++stg == 3) stg = 0;
    }

    // ---- epilogue ----
    const int r0 = lane >> 2, cc = (lane & 3)*2;
    if (EPI == 1){
        #pragma unroll
        for (int i=0;i<4;i++){
            int row = bm + wm + i*16 + r0;
            #pragma unroll
            for (int j=0;j<8;j++){
                int col = bn + wn + j*8 + cc;
                float v0 = acc[i][j][0], v1 = acc[i][j][1];
                float v2 = acc[i][j][2], v3 = acc[i][j][3];
                float2 d2 = *(const float2*)(e1 + col);
                __half2 h0 = *(const __half2*)(e0h + (size_t)row*CDIM + col);
                __half2 l0 = *(const __half2*)(e0l + (size_t)row*CDIM + col);
                __half2 h1 = *(const __half2*)(e0h + (size_t)(row+8)*CDIM + col);
                __half2 l1 = *(const __half2*)(e0l + (size_t)(row+8)*CDIM + col);
                float f0x = __half2float(h0.x) + __half2float(l0.x);
                float f0y = __half2float(h0.y) + __half2float(l0.y);
                float f1x = __half2float(h1.x) + __half2float(l1.x);
                float f1y = __half2float(h1.y) + __half2float(l1.y);
                v0 = gelu_f(v0 + d2.x*f0x) + f0x;
                v1 = gelu_f(v1 + d2.y*f0y) + f0y;
                v2 = gelu_f(v2 + d2.x*f1x) + f1x;
                v3 = gelu_f(v3 + d2.y*f1y) + f1y;
                *(float2*)(Cout + (size_t)row*Nout + col)     = make_float2(v0, v1);
                *(float2*)(Cout + (size_t)(row+8)*Nout + col) = make_float2(v2, v3);
            }
        }
    } else if (EPI == 3){
        // GEGLU: even col = z1, odd col = z2 (interleaved W_enc); stage hi in smem
        __half* sth = (__half*)smem;    // [128 rows][72 halves stride]
        __syncthreads();
        #pragma unroll
        for (int i=0;i<4;i++){
            int rl = wm + i*16 + r0;
            #pragma unroll
            for (int j=0;j<8;j++){
                int gcl = (wn >> 1) + j*4 + (lane & 3);
                float g0 = acc[i][j][0] * gelu_f(acc[i][j][1]);
                float g1 = acc[i][j][2] * gelu_f(acc[i][j][3]);
                sth[rl*72 + gcl]     = __float2half_rn(g0);
                sth[(rl+8)*72 + gcl] = __float2half_rn(g1);
            }
        }
        __syncthreads();
        int gcol0 = bn >> 1;
        #pragma unroll
        for (int q = 0; q < 32; q++){
            int rl = w*32 + q;
            uint32_t v = *(const uint32_t*)(sth + rl*72 + 2*lane);
            *(uint32_t*)(outH + (size_t)(bm + rl)*CDIM + gcol0 + 2*lane) = v;
        }
    } else if (EPI == 4){
        // residual add then transposed store to [B, C, L] via smem staging
        float* smf = (float*)smem;      // [128 cols][132 row-stride]
        __syncthreads();
        #pragma unroll
        for (int i=0;i<4;i++){
            int row = bm + wm + i*16 + r0;
            int rl  = wm + i*16 + r0;
            #pragma unroll
            for (int j=0;j<8;j++){
                int col = bn + wn + j*8 + cc;
                int clo = wn + j*8 + cc;
                __half2 h0 = *(const __half2*)(e0h + (size_t)row*CDIM + col);
                __half2 l0 = *(const __half2*)(e0l + (size_t)row*CDIM + col);
                __half2 h1 = *(const __half2*)(e0h + (size_t)(row+8)*CDIM + col);
                __half2 l1 = *(const __half2*)(e0l + (size_t)(row+8)*CDIM + col);
                smf[(clo  )*132 + rl    ] = acc[i][j][0] + __half2float(h0.x) + __half2float(l0.x);
                smf[(clo+1)*132 + rl    ] = acc[i][j][1] + __half2float(h0.y) + __half2float(l0.y);
                smf[(clo  )*132 + rl + 8] = acc[i][j][2] + __half2float(h1.x) + __half2float(l1.x);
                smf[(clo+1)*132 + rl + 8] = acc[i][j][3] + __half2float(h1.y) + __half2float(l1.y);
            }
        }
        __syncthreads();
        int b  = bm >> 12;
        int l0 = bm & 4095;
        #pragma unroll
        for (int q = 0; q < 32; q++){
            int cl = w*32 + q;
            float4 v = *(const float4*)(smf + cl*132 + lane*4);
            *(float4*)(Cout + ((size_t)b*CDIM + bn + cl)*LDIM + l0 + lane*4) = v;
        }
    } else {
        // EPI 5: plain fp16 store
        #pragma unroll
        for (int i=0;i<4;i++){
            int row = bm + wm + i*16 + r0;
            #pragma unroll
            for (int j=0;j<8;j++){
                int col = bn + wn + j*8 + cc;
                __half2 v01 = __floats2half2_rn(acc[i][j][0], acc[i][j][1]);
                __half2 v23 = __floats2half2_rn(acc[i][j][2], acc[i][j][3]);
                *(__half2*)(outH + (size_t)row*Nout + col)     = v01;
                *(__half2*)(outH + (size_t)(row+8)*Nout + col) = v23;
            }
        }
    }
}

// ---------------- prep: discretization (must run first; others read g_lam) ----------------
__global__ void prep_lam(const float* __restrict__ Lam, const float* __restrict__ logstep){
    int p = threadIdx.x;
    float step = expf(logstep[p]);
    float lre = Lam[2*p], lim = Lam[2*p+1];
    double a  = exp((double)lre*(double)step);
    double th = (double)lim*(double)step;
    g_lam[2*p]   = (float)(a*cos(th));
    g_lam[2*p+1] = (float)(a*sin(th));
    double aT  = exp((double)TCH*(double)lre*(double)step);
    double thT = (double)TCH*th;
    g_lamT[2*p]   = (float)(aT*cos(thT));
    g_lamT[2*p+1] = (float)(aT*sin(thT));
}

// one kernel for all weight preps: wb(192) | wc(384) | we(768) | wd(384) blocks
__global__ void prep_all(const float* __restrict__ Lam, const float* __restrict__ logstep,
                         const float* __restrict__ Bmat, const float* __restrict__ Cmat,
                         const float* __restrict__ Wenc, const float* __restrict__ Wdec){
    int bid = blockIdx.x, tid = threadIdx.x;
    if (bid < 192){
        int p = bid, c = tid;
        float lre = Lam[2*p], lim = Lam[2*p+1];
        float lbr = g_lam[2*p], lbi = g_lam[2*p+1];
        float den = lre*lre + lim*lim;
        float cr = ((lbr-1.0f)*lre + lbi*lim)/den;
        float ci = (lbi*lre - (lbr-1.0f)*lim)/den;
        float br = Bmat[(p*CDIM + c)*2], bi = Bmat[(p*CDIM + c)*2 + 1];
        g_wb[(size_t)p*CDIM + c]        = __float2half_rn(cr*br - ci*bi);
        g_wb[(size_t)(PDIM+p)*CDIM + c] = __float2half_rn(cr*bi + ci*br);
    } else if (bid < 576){
        if (tid < PDIM){
            int hrow = bid - 192, p = tid;
            float step = expf(logstep[p]);
            float lim = Lam[2*p+1];
            float freq = step*fabsf(lim)*(float)(1.0/(2.0*3.14159265358979323846));
            float m = (freq < 0.25f) ? 2.0f : 0.0f;
            float cre = Cmat[(hrow*PDIM + p)*2], cim = Cmat[(hrow*PDIM + p)*2 + 1];
            g_wc[(size_t)hrow*CDIM + p]        = __float2half_rn( m*cre);
            g_wc[(size_t)hrow*CDIM + PDIM + p] = __float2half_rn(-m*cim);
        }
    } else if (bid < 1344){
        int n = bid - 576, c = tid;
        int src = (n & 1) ? (CDIM + (n >> 1)) : (n >> 1);
        g_we[(size_t)n*CDIM + c] = __float2half_rn(Wenc[(size_t)src*CDIM + c]);
    } else {
        int i = (bid - 1344)*CDIM + tid;   // 384 blocks x 384 = 147456 exactly
        g_wd[i] = __float2half_rn(Wdec[i]);
    }
}

// ---------------- LayerNorm 1 : x[B,C,L] -> hi/lo fp16 [BL,C] ----------------
__global__ __launch_bounds__(256) void ln1_kernel(const float* __restrict__ x,
                                                  const float* __restrict__ gam,
                                                  const float* __restrict__ bet,
                                                  __half* __restrict__ fxh,
                                                  __half* __restrict__ fxl){
    __shared__ float tile[CDIM][17];
    int b = blockIdx.y, l0 = blockIdx.x*16;
    int tid = threadIdx.x;
    for (int idx = tid; idx < CDIM*16; idx += 256){
        int c = idx >> 4, j = idx & 15;
        tile[c][j] = x[((size_t)b*CDIM + c)*LDIM + l0 + j];
    }
    __syncthreads();
    int w = tid >> 5, lane = tid & 31;
    for (int j = w*2; j < w*2 + 2; j++){
        float v[12]; float s = 0.0f;
        #pragma unroll
        for (int k = 0; k < 12; k++){ v[k] = tile[lane + 32*k][j]; s += v[k]; }
        #pragma unroll
        for (int o = 16; o; o >>= 1) s += __shfl_xor_sync(0xffffffffu, s, o);
        float mu = s * (1.0f/CDIM);
        float q = 0.0f;
        #pragma unroll
        for (int k = 0; k < 12; k++){ float d = v[k]-mu; q += d*d; }
        #pragma unroll
        for (int o = 16; o; o >>= 1) q += __shfl_xor_sync(0xffffffffu, q, o);
        float inv = rsqrtf(q*(1.0f/CDIM) + 1e-5f);
        size_t row = ((size_t)b*LDIM + l0 + j)*CDIM;
        #pragma unroll
        for (int k = 0; k < 12; k++){
            int c = lane + 32*k;
            float val = (v[k]-mu)*inv*gam[c] + bet[c];
            __half h,l; split_hl(val,h,l);
            fxh[row + c] = h; fxl[row + c] = l;
        }
    }
}

// ---------------- LayerNorm 2 : y[BL,C] -> hi/lo ----------------
__global__ __launch_bounds__(256) void ln2_kernel(const float* __restrict__ y,
                                                  const float* __restrict__ gam,
                                                  const float* __restrict__ bet,
                                                  __half* __restrict__ fyh,
                                                  __half* __restrict__ fyl){
    int row = blockIdx.x*8 + (threadIdx.x >> 5);
    int lane = threadIdx.x & 31;
    const float4* r4 = (const float4*)(y + (size_t)row*CDIM);
    float4 v[3]; float s = 0.0f;
    #pragma unroll
    for (int k = 0; k < 3; k++){ v[k] = r4[lane + 32*k]; s += v[k].x+v[k].y+v[k].z+v[k].w; }
    #pragma unroll
    for (int o = 16; o; o >>= 1) s += __shfl_xor_sync(0xffffffffu, s, o);
    float mu = s * (1.0f/CDIM);
    float q = 0.0f;
    #pragma unroll
    for (int k = 0; k < 3; k++){
        float dx=v[k].x-mu, dy=v[k].y-mu, dz=v[k].z-mu, dw=v[k].w-mu;
        q += dx*dx+dy*dy+dz*dz+dw*dw;
    }
    #pragma unroll
    for (int o = 16; o; o >>= 1) q += __shfl_xor_sync(0xffffffffu, q, o);
    float inv = rsqrtf(q*(1.0f/CDIM) + 1e-5f);
    #pragma unroll
    for (int k = 0; k < 3; k++){
        int c4 = lane + 32*k;
        float4 gg = ((const float4*)gam)[c4], bb = ((const float4*)bet)[c4];
        float rx = (v[k].x-mu)*inv*gg.x + bb.x;
        float ry = (v[k].y-mu)*inv*gg.y + bb.y;
        float rz = (v[k].z-mu)*inv*gg.z + bb.z;
        float rw = (v[k].w-mu)*inv*gg.w + bb.w;
        size_t base = (size_t)row*CDIM + c4*4;
        __half h,l;
        split_hl(rx,h,l); fyh[base+0]=h; fyl[base+0]=l;
        split_hl(ry,h,l); fyh[base+1]=h; fyl[base+1]=l;
        split_hl(rz,h,l); fyh[base+2]=h; fyl[base+2]=l;
        split_hl(rw,h,l); fyh[base+3]=h; fyl[base+3]=l;
    }
}

// ---------------- chunked constant-coefficient complex scan (fp16 Bu) ----------------
__global__ void scan_a(const __half* __restrict__ bu, float* __restrict__ carry){
    int p = threadIdx.x, ch = blockIdx.x, b = blockIdx.y;
    float lre = g_lam[2*p], lim = g_lam[2*p+1];
    float sre = 0.0f, sim = 0.0f;
    size_t base = ((size_t)b*LDIM + (size_t)ch*TCH)*CDIM;
    for (int i = 0; i < TCH; i++){
        size_t idx = base + (size_t)i*CDIM;
        float br = __half2float(bu[idx+p]), bi = __half2float(bu[idx+PDIM+p]);
        float nr = fmaf(lre, sre, fmaf(-lim, sim, br));
        float ni = fmaf(lre, sim, fmaf( lim, sre, bi));
        sre = nr; sim = ni;
    }
    size_t cidx = ((size_t)b*NCH + ch)*CDIM;
    carry[cidx+p] = sre; carry[cidx+PDIM+p] = sim;
}

// scan_c: compose prefix from raw carries (scan_b folded in), run local recurrence, emit fp16
__global__ void scan_c(const __half* __restrict__ bu, const float* __restrict__ carry,
                       __half* __restrict__ bh){
    int p = threadIdx.x, ch = blockIdx.x, b = blockIdx.y;
    float tr = g_lamT[2*p], ti = g_lamT[2*p+1];
    float sre = 0.0f, sim = 0.0f;
    for (int k = 0; k < ch; k++){
        size_t ci = ((size_t)b*NCH + k)*CDIM;
        float cr = carry[ci+p], cm = carry[ci+PDIM+p];
        float nr = fmaf(tr, sre, fmaf(-ti, sim, cr));
        float ni = fmaf(tr, sim, fmaf( ti, sre, cm));
        sre = nr; sim = ni;
    }
    float lre = g_lam[2*p], lim = g_lam[2*p+1];
    size_t base = ((size_t)b*LDIM + (size_t)ch*TCH)*CDIM;
    for (int i = 0; i < TCH; i++){
        size_t idx = base + (size_t)i*CDIM;
        float br = __half2float(bu[idx+p]), bi = __half2float(bu[idx+PDIM+p]);
        float nr = fmaf(lre, sre, fmaf(-lim, sim, br));
        float ni = fmaf(lre, sim, fmaf( lim, sre, bi));
        sre = nr; sim = ni;
        bh[idx+p]      = __float2half_rn(nr);
        bh[idx+PDIM+p] = __float2half_rn(ni);
    }
}

// ---------------- launch ----------------
extern "C" void kernel_launch(void* const* d_in, const int* in_sizes, int n_in,
                              void* d_out, int out_size){
    const float* x       = (const float*)d_in[0];
    const float* ln1g    = (const float*)d_in[1];
    const float* ln1b    = (const float*)d_in[2];
    const float* Lam     = (const float*)d_in[3];
    const float* Bmat    = (const float*)d_in[4];
    const float* Cmat    = (const float*)d_in[5];
    const float* Dv      = (const float*)d_in[6];
    const float* logstep = (const float*)d_in[7];
    const float* ln2g    = (const float*)d_in[8];
    const float* ln2b    = (const float*)d_in[9];
    const float* Wenc    = (const float*)d_in[10];
    const float* Wdec    = (const float*)d_in[11];
    float* out = (float*)d_out;

    float *y,*carry;
    cudaGetSymbolAddress((void**)&y,     g_y);
    cudaGetSymbolAddress((void**)&carry, g_carry);

    __half *buf,*fxh,*fxl,*buh,*fyh,*fyl,*ggh,*wb,*wc,*we,*wd;
    cudaGetSymbolAddress((void**)&buf, g_buf);
    cudaGetSymbolAddress((void**)&fxh, g_fxh); cudaGetSymbolAddress((void**)&fxl, g_fxl);
    cudaGetSymbolAddress((void**)&buh, g_buh);
    cudaGetSymbolAddress((void**)&fyh, g_fyh); cudaGetSymbolAddress((void**)&fyl, g_fyl);
    cudaGetSymbolAddress((void**)&ggh, g_ggh);
    cudaGetSymbolAddress((void**)&wb,  g_wb);  cudaGetSymbolAddress((void**)&wc,  g_wc);
    cudaGetSymbolAddress((void**)&we,  g_we);  cudaGetSymbolAddress((void**)&wd,  g_wd);

    const int SMEM_GEMM = 3*36864;   // 110592 B (3-stage BK=64; covers EPI staging)
    cudaFuncSetAttribute(mma_gemm<1>, cudaFuncAttributeMaxDynamicSharedMemorySize, SMEM_GEMM);
    cudaFuncSetAttribute(mma_gemm<3>, cudaFuncAttributeMaxDynamicSharedMemorySize, SMEM_GEMM);
    cudaFuncSetAttribute(mma_gemm<4>, cudaFuncAttributeMaxDynamicSharedMemorySize, SMEM_GEMM);
    cudaFuncSetAttribute(mma_gemm<5>, cudaFuncAttributeMaxDynamicSharedMemorySize, SMEM_GEMM);

    // launch 1-2: prep
    prep_lam<<<1, PDIM>>>(Lam, logstep);
    prep_all<<<1728, CDIM>>>(Lam, logstep, Bmat, Cmat, Wenc, Wdec);

    // launch 3
    ln1_kernel<<<dim3(LDIM/16, BSZ), 256>>>(x, ln1g, ln1b, fxh, fxl);

    // launch 4 (ncu capture slot): Bu = fx @ Bbar^T -> fp16 [BL, 2P]
    mma_gemm<5><<<dim3(3, 512), 128, SMEM_GEMM>>>(fxh, wb, nullptr, CDIM,
                                                  buf, nullptr, nullptr, nullptr);

    // launch 5-6: scan
    scan_a<<<dim3(NCH, BSZ), PDIM>>>(buf, carry);
    scan_c<<<dim3(NCH, BSZ), PDIM>>>(buf, carry, buh);

    // launch 7: y = gelu(xs @ Ceff^T + D*fx) + fx
    mma_gemm<1><<<dim3(3, 512), 128, SMEM_GEMM>>>(buh, wc, y, CDIM,
                                                  nullptr, fxh, fxl, Dv);

    // launch 8
    ln2_kernel<<<BLTOK/8, 256>>>(y, ln2g, ln2b, fyh, fyl);

    // launch 9: gg = GEGLU(fy @ Wenc_interleaved^T) -> fp16 [BL, 384]
    mma_gemm<3><<<dim3(6, 512), 128, SMEM_GEMM>>>(fyh, we, nullptr, CDIM,
                                                  ggh, nullptr, nullptr, nullptr);

    // launch 10: out = transpose(gg @ Wdec^T + fy) -> [B,C,L]
    mma_gemm<4><<<dim3(3, 512), 128, SMEM_GEMM>>>(ggh, wd, out, CDIM,
                                                  nullptr, fyh, fyl, nullptr);
}